// round 14
// baseline (speedup 1.0000x reference)
#include <cuda_runtime.h>
#include <math.h>

#define N_SRC 20000
#define M_Q   40000
#define N_ALL 60000
#define CF    64
#define HF    128
#define TS    2048

__device__ float g_stats[6];            // mu[3], sd[3]
__device__ float g_fi[(size_t)M_Q * CF];

// ---------------------------------------------------------------------------
// Kernel 1: stats (mean/std ddof=1), F2 bit-family schedule (row-reduce,
// 1024 threads, vector_size=2). Produces bits identical to the 245-tree and
// 246x244 schedules (verified: R9 ≡ R12 to 7 digits) — a stable natural
// rounding of this reduction, matching XLA-GPU's reduction emitter.
// ---------------------------------------------------------------------------
__device__ __forceinline__ float load_col(const float* __restrict__ coords,
                                          const float* __restrict__ gt,
                                          int r, int c)
{
    return (r < M_Q) ? gt[r * 3 + c] : coords[(r - M_Q) * 3 + c];
}

__global__ void __launch_bounds__(1024) stats_rowred_kernel(
    const float* __restrict__ coords, const float* __restrict__ gt)
{
    const int c    = blockIdx.x;            // column 0..2
    const int t    = threadIdx.x;           // 0..1023
    const int lane = t & 31;
    const int w    = t >> 5;                // warp 0..31
    __shared__ float part[32];
    __shared__ float smu;

    // ---------------- mean pass ----------------
    float a0 = 0.f, a1 = 0.f;
    for (int i = 0; i < 30; i++) {
        const int e0 = 2 * t + 2048 * i;
        const int e1 = e0 + 1;
        if (e0 < N_ALL) a0 = __fadd_rn(a0, load_col(coords, gt, e0, c));
        if (e1 < N_ALL) a1 = __fadd_rn(a1, load_col(coords, gt, e1, c));
    }
    float p = __fadd_rn(a0, a1);
#pragma unroll
    for (int off = 16; off; off >>= 1)
        p = __fadd_rn(p, __shfl_down_sync(0xffffffffu, p, off));
    if (lane == 0) part[w] = p;
    __syncthreads();
    if (w == 0) {
        float v = part[lane];
#pragma unroll
        for (int off = 16; off; off >>= 1)
            v = __fadd_rn(v, __shfl_down_sync(0xffffffffu, v, off));
        if (lane == 0) {
            smu = __fdiv_rn(v, 60000.0f);
            g_stats[c] = smu;
        }
    }
    __syncthreads();
    const float mu = smu;

    // ---------------- var pass ----------------
    a0 = 0.f; a1 = 0.f;
    for (int i = 0; i < 30; i++) {
        const int e0 = 2 * t + 2048 * i;
        const int e1 = e0 + 1;
        if (e0 < N_ALL) {
            const float d = __fsub_rn(load_col(coords, gt, e0, c), mu);
            a0 = __fadd_rn(a0, __fmul_rn(d, d));
        }
        if (e1 < N_ALL) {
            const float d = __fsub_rn(load_col(coords, gt, e1, c), mu);
            a1 = __fadd_rn(a1, __fmul_rn(d, d));
        }
    }
    p = __fadd_rn(a0, a1);
#pragma unroll
    for (int off = 16; off; off >>= 1)
        p = __fadd_rn(p, __shfl_down_sync(0xffffffffu, p, off));
    if (lane == 0) part[w] = p;
    __syncthreads();
    if (w == 0) {
        float v = part[lane];
#pragma unroll
        for (int off = 16; off; off >>= 1)
            v = __fadd_rn(v, __shfl_down_sync(0xffffffffu, v, off));
        if (lane == 0) {
            float sd = __fsqrt_rn(__fdiv_rn(v, 59999.0f));
            if (fabsf(sd) < 1e-8f) sd = 1.0f;
            g_stats[3 + c] = sd;
        }
    }
}

// ---------------------------------------------------------------------------
// Kernel 2: brute-force KNN (K=3) + softmax-weighted interpolation.
// F2 stats bits + NO-FMA dot (XLA loop-fusion, no fp contraction):
//   standardize by div.rn,
//   q2/s2 = ((x*x + y*y) + z*z)          (separate mul/add),
//   dot   = ((qx*sx + qy*sy) + qz*sz)    (separate mul/add, NO fma),
//   d2    = (q2 + s2) - (t + t).
// Top-3 on d2, strict '<' (stable low-index ties; d2-domain selection proven
// equivalent to D-domain on this data, R10 ≡ R11).
// ---------------------------------------------------------------------------
__device__ __forceinline__ void ins3(float d, int sidx,
                                     float& t0, float& t1, float& t2,
                                     int& i0, int& i1, int& i2)
{
    if (d < t2) {
        if (d < t1) {
            t2 = t1; i2 = i1;
            if (d < t0) { t1 = t0; i1 = i0; t0 = d; i0 = sidx; }
            else        { t1 = d;  i1 = sidx; }
        } else { t2 = d; i2 = sidx; }
    }
}

__device__ __forceinline__ float pair_d2(float qx, float qy, float qz, float q2,
                                         const float4 v)
{
    const float m0 = __fmul_rn(qx, v.x);
    const float m1 = __fmul_rn(qy, v.y);
    const float m2 = __fmul_rn(qz, v.z);
    const float t  = __fadd_rn(__fadd_rn(m0, m1), m2);
    const float u  = __fadd_rn(q2, v.w);
    return __fsub_rn(u, __fadd_rn(t, t));
}

__global__ void __launch_bounds__(256) knn_kernel(
    const float* __restrict__ coords, const float* __restrict__ feats,
    const float* __restrict__ gt)
{
    __shared__ float4 tile[TS];

    const float mux = g_stats[0], muy = g_stats[1], muz = g_stats[2];
    const float sdx = g_stats[3], sdy = g_stats[4], sdz = g_stats[5];

    const int q = blockIdx.x * blockDim.x + threadIdx.x;
    const bool valid = (q < M_Q);

    float qx = 0.f, qy = 0.f, qz = 0.f, q2 = 0.f;
    if (valid) {
        qx = __fdiv_rn(__fsub_rn(gt[q * 3 + 0], mux), sdx);
        qy = __fdiv_rn(__fsub_rn(gt[q * 3 + 1], muy), sdy);
        qz = __fdiv_rn(__fsub_rn(gt[q * 3 + 2], muz), sdz);
        q2 = __fadd_rn(__fadd_rn(__fmul_rn(qx, qx), __fmul_rn(qy, qy)),
                       __fmul_rn(qz, qz));
    }

    float t0 = 3.4e38f, t1 = 3.4e38f, t2 = 3.4e38f;
    int   i0 = 0, i1 = 0, i2 = 0;

    for (int base = 0; base < N_SRC; base += TS) {
        __syncthreads();
        for (int j = threadIdx.x; j < TS; j += blockDim.x) {
            const int sidx = base + j;
            float4 v;
            if (sidx < N_SRC) {
                float x = __fdiv_rn(__fsub_rn(coords[sidx * 3 + 0], mux), sdx);
                float y = __fdiv_rn(__fsub_rn(coords[sidx * 3 + 1], muy), sdy);
                float z = __fdiv_rn(__fsub_rn(coords[sidx * 3 + 2], muz), sdz);
                float s2 = __fadd_rn(__fadd_rn(__fmul_rn(x, x), __fmul_rn(y, y)),
                                     __fmul_rn(z, z));
                v = make_float4(x, y, z, s2);
            } else {
                v = make_float4(0.f, 0.f, 0.f, 3.0e38f);
            }
            tile[j] = v;
        }
        __syncthreads();

#pragma unroll 4
        for (int j = 0; j < TS; j += 4) {
            const float d0 = pair_d2(qx, qy, qz, q2, tile[j + 0]);
            const float d1 = pair_d2(qx, qy, qz, q2, tile[j + 1]);
            const float d2 = pair_d2(qx, qy, qz, q2, tile[j + 2]);
            const float d3 = pair_d2(qx, qy, qz, q2, tile[j + 3]);
            const float m = fminf(fminf(d0, d1), fminf(d2, d3));
            if (m < t2) {
                ins3(d0, base + j + 0, t0, t1, t2, i0, i1, i2);
                ins3(d1, base + j + 1, t0, t1, t2, i0, i1, i2);
                ins3(d2, base + j + 2, t0, t1, t2, i0, i1, i2);
                ins3(d3, base + j + 3, t0, t1, t2, i0, i1, i2);
            }
        }
    }

    if (!valid) return;

    const float b0 = __fsqrt_rn(fmaxf(t0, 0.f));
    const float b1 = __fsqrt_rn(fmaxf(t1, 0.f));
    const float b2 = __fsqrt_rn(fmaxf(t2, 0.f));
    const float mean3 = __fdiv_rn(__fadd_rn(__fadd_rn(b0, b1), b2), 3.0f);
    const float scale = fmaxf(mean3, 1e-8f);
    const float e1 = expf(-__fdiv_rn(__fsub_rn(b1, b0), scale));
    const float e2 = expf(-__fdiv_rn(__fsub_rn(b2, b0), scale));
    const float sum = __fadd_rn(__fadd_rn(1.0f, e1), e2);
    const float w0 = __fdiv_rn(1.0f, sum);
    const float w1 = __fdiv_rn(e1, sum);
    const float w2 = __fdiv_rn(e2, sum);

    const float4* f0 = (const float4*)(feats + (size_t)i0 * CF);
    const float4* f1 = (const float4*)(feats + (size_t)i1 * CF);
    const float4* f2 = (const float4*)(feats + (size_t)i2 * CF);
    float4* outp = (float4*)(g_fi + (size_t)q * CF);
#pragma unroll
    for (int k = 0; k < CF / 4; k++) {
        const float4 A = f0[k], B = f1[k], Cc = f2[k];
        float4 r;
        r.x = __fadd_rn(__fadd_rn(__fmul_rn(w0, A.x), __fmul_rn(w1, B.x)), __fmul_rn(w2, Cc.x));
        r.y = __fadd_rn(__fadd_rn(__fmul_rn(w0, A.y), __fmul_rn(w1, B.y)), __fmul_rn(w2, Cc.y));
        r.z = __fadd_rn(__fadd_rn(__fmul_rn(w0, A.z), __fmul_rn(w1, B.z)), __fmul_rn(w2, Cc.z));
        r.w = __fadd_rn(__fadd_rn(__fmul_rn(w0, A.w), __fmul_rn(w1, B.w)), __fmul_rn(w2, Cc.w));
        outp[k] = r;
    }
}

// ---------------------------------------------------------------------------
// Kernel 3: per-row MLP (plain fp32). Smooth — sub-threshold either mode.
// ---------------------------------------------------------------------------
__global__ void __launch_bounds__(128) mlp_kernel(
    const float* __restrict__ W1, const float* __restrict__ b1,
    const float* __restrict__ g1, const float* __restrict__ be1,
    const float* __restrict__ W2, const float* __restrict__ b2,
    const float* __restrict__ gf, const float* __restrict__ bf,
    float* __restrict__ outf)
{
    __shared__ float sW1[CF * HF];
    __shared__ float sb1[HF], sg1[HF], sbe1[HF];
    __shared__ float sb2[CF], sgf[CF], sbf[CF];
    __shared__ float sfi[CF], sh[HF];
    __shared__ float sred[8];

    const int tid = threadIdx.x;
    for (int i = tid; i < CF * HF; i += blockDim.x) sW1[i] = W1[i];
    if (tid < HF) { sb1[tid] = b1[tid]; sg1[tid] = g1[tid]; sbe1[tid] = be1[tid]; }
    if (tid < CF) { sb2[tid] = b2[tid]; sgf[tid] = gf[tid]; sbf[tid] = bf[tid]; }
    __syncthreads();

    const int w = tid >> 5, l = tid & 31;

    for (int row = blockIdx.x; row < M_Q; row += gridDim.x) {
        if (tid < CF) sfi[tid] = g_fi[(size_t)row * CF + tid];
        __syncthreads();

        float acc = 0.f;
#pragma unroll 16
        for (int c = 0; c < CF; c++) acc = __fmaf_rn(sfi[c], sW1[c * HF + tid], acc);
        const float x = fmaxf(__fadd_rn(acc, sb1[tid]), 0.f);

        float s = x, ssq = x * x;
        for (int o = 16; o; o >>= 1) {
            s   += __shfl_down_sync(0xffffffffu, s, o);
            ssq += __shfl_down_sync(0xffffffffu, ssq, o);
        }
        if (l == 0) { sred[w] = s; sred[4 + w] = ssq; }
        __syncthreads();
        {
            const float S  = sred[0] + sred[1] + sred[2] + sred[3];
            const float SS = sred[4] + sred[5] + sred[6] + sred[7];
            const float mu  = S * (1.0f / HF);
            const float var = SS * (1.0f / HF) - mu * mu;
            const float rstd = 1.0f / sqrtf(var + 1e-5f);
            sh[tid] = (x - mu) * rstd * sg1[tid] + sbe1[tid];
        }
        __syncthreads();

        float fo = 0.f;
        if (tid < CF) {
            float a2 = 0.f;
#pragma unroll 16
            for (int h = 0; h < HF; h++) a2 = __fmaf_rn(sh[h], W2[h * CF + tid], a2);
            fo = __fadd_rn(__fadd_rn(a2, sb2[tid]), sfi[tid]);
        }

        float s2 = (tid < CF) ? fo : 0.f;
        float ss2 = s2 * s2;
        for (int o = 16; o; o >>= 1) {
            s2  += __shfl_down_sync(0xffffffffu, s2, o);
            ss2 += __shfl_down_sync(0xffffffffu, ss2, o);
        }
        if (l == 0) { sred[w] = s2; sred[4 + w] = ss2; }
        __syncthreads();
        {
            const float S  = sred[0] + sred[1] + sred[2] + sred[3];
            const float SS = sred[4] + sred[5] + sred[6] + sred[7];
            const float mu  = S * (1.0f / CF);
            const float var = SS * (1.0f / CF) - mu * mu;
            const float rstd = 1.0f / sqrtf(var + 1e-5f);
            if (tid < CF) {
                const float z = (fo - mu) * rstd * sgf[tid] + sbf[tid];
                outf[(size_t)row * CF + tid] = tanhf(z) * 6.0f;
            }
        }
        __syncthreads();
    }
}

// ---------------------------------------------------------------------------
// Kernel 4: pass-through copy of gt_coords into the output head.
// ---------------------------------------------------------------------------
__global__ void copy_kernel(const float* __restrict__ src, float* __restrict__ dst, int n)
{
    int i = blockIdx.x * blockDim.x + threadIdx.x;
    if (i < n) dst[i] = src[i];
}

extern "C" void kernel_launch(void* const* d_in, const int* in_sizes, int n_in,
                              void* d_out, int out_size)
{
    const float* coords = (const float*)d_in[0];
    const float* feats  = (const float*)d_in[1];
    const float* gt     = (const float*)d_in[2];
    const float* W1     = (const float*)d_in[3];
    const float* b1     = (const float*)d_in[4];
    const float* g1     = (const float*)d_in[5];
    const float* be1    = (const float*)d_in[6];
    const float* W2     = (const float*)d_in[7];
    const float* b2     = (const float*)d_in[8];
    const float* gf     = (const float*)d_in[9];
    const float* bf     = (const float*)d_in[10];

    float* out = (float*)d_out;
    float* out_feats = out;

    if (out_size >= M_Q * 3 + M_Q * CF) {
        copy_kernel<<<(M_Q * 3 + 255) / 256, 256>>>(gt, out, M_Q * 3);
        out_feats = out + M_Q * 3;
    }

    stats_rowred_kernel<<<3, 1024>>>(coords, gt);
    knn_kernel<<<(M_Q + 255) / 256, 256>>>(coords, feats, gt);
    mlp_kernel<<<592, 128>>>(W1, b1, g1, be1, W2, b2, gf, bf, out_feats);
}

// round 15
// speedup vs baseline: 1.5797x; 1.5797x over previous
#include <cuda_runtime.h>
#include <math.h>

#define N_SRC 20000
#define M_Q   40000
#define N_ALL 60000
#define CF    64
#define HF    128
#define NSPLIT 5
#define SPLEN  4000          // N_SRC / NSPLIT
#define TS     2000          // tile: SPLEN = 2*TS exactly (no padding)

__device__ float g_stats[6];                 // mu[3], sd[3]
__device__ float g_fi[(size_t)M_Q * CF];     // interpolated features
__device__ float4 g_src[N_SRC];              // standardized sources + s2
__device__ float g_pd[(size_t)M_Q * NSPLIT * 3];  // partial top-3 dists
__device__ int   g_pi[(size_t)M_Q * NSPLIT * 3];  // partial top-3 indices

// ---------------------------------------------------------------------------
// Kernel 1: stats — F2 bit-family (row-reduce 1024 thr, vec=2). LOCKED.
// ---------------------------------------------------------------------------
__device__ __forceinline__ float load_col(const float* __restrict__ coords,
                                          const float* __restrict__ gt,
                                          int r, int c)
{
    return (r < M_Q) ? gt[r * 3 + c] : coords[(r - M_Q) * 3 + c];
}

__global__ void __launch_bounds__(1024) stats_rowred_kernel(
    const float* __restrict__ coords, const float* __restrict__ gt)
{
    const int c    = blockIdx.x;
    const int t    = threadIdx.x;
    const int lane = t & 31;
    const int w    = t >> 5;
    __shared__ float part[32];
    __shared__ float smu;

    float a0 = 0.f, a1 = 0.f;
    for (int i = 0; i < 30; i++) {
        const int e0 = 2 * t + 2048 * i;
        const int e1 = e0 + 1;
        if (e0 < N_ALL) a0 = __fadd_rn(a0, load_col(coords, gt, e0, c));
        if (e1 < N_ALL) a1 = __fadd_rn(a1, load_col(coords, gt, e1, c));
    }
    float p = __fadd_rn(a0, a1);
#pragma unroll
    for (int off = 16; off; off >>= 1)
        p = __fadd_rn(p, __shfl_down_sync(0xffffffffu, p, off));
    if (lane == 0) part[w] = p;
    __syncthreads();
    if (w == 0) {
        float v = part[lane];
#pragma unroll
        for (int off = 16; off; off >>= 1)
            v = __fadd_rn(v, __shfl_down_sync(0xffffffffu, v, off));
        if (lane == 0) { smu = __fdiv_rn(v, 60000.0f); g_stats[c] = smu; }
    }
    __syncthreads();
    const float mu = smu;

    a0 = 0.f; a1 = 0.f;
    for (int i = 0; i < 30; i++) {
        const int e0 = 2 * t + 2048 * i;
        const int e1 = e0 + 1;
        if (e0 < N_ALL) {
            const float d = __fsub_rn(load_col(coords, gt, e0, c), mu);
            a0 = __fadd_rn(a0, __fmul_rn(d, d));
        }
        if (e1 < N_ALL) {
            const float d = __fsub_rn(load_col(coords, gt, e1, c), mu);
            a1 = __fadd_rn(a1, __fmul_rn(d, d));
        }
    }
    p = __fadd_rn(a0, a1);
#pragma unroll
    for (int off = 16; off; off >>= 1)
        p = __fadd_rn(p, __shfl_down_sync(0xffffffffu, p, off));
    if (lane == 0) part[w] = p;
    __syncthreads();
    if (w == 0) {
        float v = part[lane];
#pragma unroll
        for (int off = 16; off; off >>= 1)
            v = __fadd_rn(v, __shfl_down_sync(0xffffffffu, v, off));
        if (lane == 0) {
            float sd = __fsqrt_rn(__fdiv_rn(v, 59999.0f));
            if (fabsf(sd) < 1e-8f) sd = 1.0f;
            g_stats[3 + c] = sd;
        }
    }
}

// ---------------------------------------------------------------------------
// Kernel 1b: pre-standardize sources once (identical bits to the per-block
// version: div.rn standardize, s2 = ((x*x + y*y) + z*z)).
// ---------------------------------------------------------------------------
__global__ void presrc_kernel(const float* __restrict__ coords)
{
    const int i = blockIdx.x * blockDim.x + threadIdx.x;
    if (i >= N_SRC) return;
    const float x = __fdiv_rn(__fsub_rn(coords[i * 3 + 0], g_stats[0]), g_stats[3]);
    const float y = __fdiv_rn(__fsub_rn(coords[i * 3 + 1], g_stats[1]), g_stats[4]);
    const float z = __fdiv_rn(__fsub_rn(coords[i * 3 + 2], g_stats[2]), g_stats[5]);
    const float s2 = __fadd_rn(__fadd_rn(__fmul_rn(x, x), __fmul_rn(y, y)),
                               __fmul_rn(z, z));
    g_src[i] = make_float4(x, y, z, s2);
}

// ---------------------------------------------------------------------------
// KNN distance + stable top-3 machinery. LOCKED numerics:
// dot = ((qx*sx + qy*sy) + qz*sz) (no fma), d2 = (q2+s2) - (t+t),
// strict '<' insertion = stable (d, idx) order.
// ---------------------------------------------------------------------------
__device__ __forceinline__ void ins3(float d, int sidx,
                                     float& t0, float& t1, float& t2,
                                     int& i0, int& i1, int& i2)
{
    if (d < t2) {
        if (d < t1) {
            t2 = t1; i2 = i1;
            if (d < t0) { t1 = t0; i1 = i0; t0 = d; i0 = sidx; }
            else        { t1 = d;  i1 = sidx; }
        } else { t2 = d; i2 = sidx; }
    }
}

__device__ __forceinline__ float pair_d2(float qx, float qy, float qz, float q2,
                                         const float4 v)
{
    const float m0 = __fmul_rn(qx, v.x);
    const float m1 = __fmul_rn(qy, v.y);
    const float m2 = __fmul_rn(qz, v.z);
    const float t  = __fadd_rn(__fadd_rn(m0, m1), m2);
    const float u  = __fadd_rn(q2, v.w);
    return __fsub_rn(u, __fadd_rn(t, t));
}

// ---------------------------------------------------------------------------
// Kernel 2a: per-split stable top-3. blockIdx.y = split (5 ranges of 4000).
// Every per-pair d2 is bit-identical to the monolithic loop; the per-split
// top-3 list is stable-(d,idx)-sorted, so the merge reproduces the global
// stable top-3 exactly.
// ---------------------------------------------------------------------------
__global__ void __launch_bounds__(256) knn_partial_kernel(
    const float* __restrict__ gt)
{
    __shared__ float4 tile[TS];

    const int split = blockIdx.y;
    const int q = blockIdx.x * blockDim.x + threadIdx.x;
    const bool valid = (q < M_Q);

    const float mux = g_stats[0], muy = g_stats[1], muz = g_stats[2];
    const float sdx = g_stats[3], sdy = g_stats[4], sdz = g_stats[5];

    float qx = 0.f, qy = 0.f, qz = 0.f, q2 = 0.f;
    if (valid) {
        qx = __fdiv_rn(__fsub_rn(gt[q * 3 + 0], mux), sdx);
        qy = __fdiv_rn(__fsub_rn(gt[q * 3 + 1], muy), sdy);
        qz = __fdiv_rn(__fsub_rn(gt[q * 3 + 2], muz), sdz);
        q2 = __fadd_rn(__fadd_rn(__fmul_rn(qx, qx), __fmul_rn(qy, qy)),
                       __fmul_rn(qz, qz));
    }

    float t0 = 3.4e38f, t1 = 3.4e38f, t2 = 3.4e38f;
    int   i0 = 0, i1 = 0, i2 = 0;

    const int sbase = split * SPLEN;
#pragma unroll
    for (int ti = 0; ti < SPLEN / TS; ti++) {
        const int base = sbase + ti * TS;
        __syncthreads();
        for (int j = threadIdx.x; j < TS; j += blockDim.x)
            tile[j] = g_src[base + j];
        __syncthreads();

#pragma unroll 4
        for (int j = 0; j < TS; j += 4) {
            const float d0 = pair_d2(qx, qy, qz, q2, tile[j + 0]);
            const float d1 = pair_d2(qx, qy, qz, q2, tile[j + 1]);
            const float d2 = pair_d2(qx, qy, qz, q2, tile[j + 2]);
            const float d3 = pair_d2(qx, qy, qz, q2, tile[j + 3]);
            const float m = fminf(fminf(d0, d1), fminf(d2, d3));
            if (m < t2) {
                ins3(d0, base + j + 0, t0, t1, t2, i0, i1, i2);
                ins3(d1, base + j + 1, t0, t1, t2, i0, i1, i2);
                ins3(d2, base + j + 2, t0, t1, t2, i0, i1, i2);
                ins3(d3, base + j + 3, t0, t1, t2, i0, i1, i2);
            }
        }
    }

    if (!valid) return;
    const size_t o = ((size_t)q * NSPLIT + split) * 3;
    g_pd[o + 0] = t0; g_pd[o + 1] = t1; g_pd[o + 2] = t2;
    g_pi[o + 0] = i0; g_pi[o + 1] = i1; g_pi[o + 2] = i2;
}

// ---------------------------------------------------------------------------
// Kernel 2b: merge partial top-3s (split-ascending = index-ascending, stable)
// + softmax weights + feature gather. Epilogue numerics LOCKED.
// ---------------------------------------------------------------------------
__global__ void __launch_bounds__(256) knn_merge_kernel(
    const float* __restrict__ feats)
{
    const int q = blockIdx.x * blockDim.x + threadIdx.x;
    if (q >= M_Q) return;

    float t0 = 3.4e38f, t1 = 3.4e38f, t2 = 3.4e38f;
    int   i0 = 0, i1 = 0, i2 = 0;
    const size_t ob = (size_t)q * NSPLIT * 3;
#pragma unroll
    for (int s = 0; s < NSPLIT * 3; s++)
        ins3(g_pd[ob + s], g_pi[ob + s], t0, t1, t2, i0, i1, i2);

    const float b0 = __fsqrt_rn(fmaxf(t0, 0.f));
    const float b1 = __fsqrt_rn(fmaxf(t1, 0.f));
    const float b2 = __fsqrt_rn(fmaxf(t2, 0.f));
    const float mean3 = __fdiv_rn(__fadd_rn(__fadd_rn(b0, b1), b2), 3.0f);
    const float scale = fmaxf(mean3, 1e-8f);
    const float e1 = expf(-__fdiv_rn(__fsub_rn(b1, b0), scale));
    const float e2 = expf(-__fdiv_rn(__fsub_rn(b2, b0), scale));
    const float sum = __fadd_rn(__fadd_rn(1.0f, e1), e2);
    const float w0 = __fdiv_rn(1.0f, sum);
    const float w1 = __fdiv_rn(e1, sum);
    const float w2 = __fdiv_rn(e2, sum);

    const float4* f0 = (const float4*)(feats + (size_t)i0 * CF);
    const float4* f1 = (const float4*)(feats + (size_t)i1 * CF);
    const float4* f2 = (const float4*)(feats + (size_t)i2 * CF);
    float4* outp = (float4*)(g_fi + (size_t)q * CF);
#pragma unroll
    for (int k = 0; k < CF / 4; k++) {
        const float4 A = f0[k], B = f1[k], Cc = f2[k];
        float4 r;
        r.x = __fadd_rn(__fadd_rn(__fmul_rn(w0, A.x), __fmul_rn(w1, B.x)), __fmul_rn(w2, Cc.x));
        r.y = __fadd_rn(__fadd_rn(__fmul_rn(w0, A.y), __fmul_rn(w1, B.y)), __fmul_rn(w2, Cc.y));
        r.z = __fadd_rn(__fadd_rn(__fmul_rn(w0, A.z), __fmul_rn(w1, B.z)), __fmul_rn(w2, Cc.z));
        r.w = __fadd_rn(__fadd_rn(__fmul_rn(w0, A.w), __fmul_rn(w1, B.w)), __fmul_rn(w2, Cc.w));
        outp[k] = r;
    }
}

// ---------------------------------------------------------------------------
// Kernel 3: per-row MLP. Same arithmetic as the passing version; W1/W2 read
// via L1 (block-invariant) instead of a 32KB smem stage -> smem 36KB -> ~3KB,
// occupancy 25% -> regs-limited. Bits unchanged.
// ---------------------------------------------------------------------------
__global__ void __launch_bounds__(128) mlp_kernel(
    const float* __restrict__ W1, const float* __restrict__ b1,
    const float* __restrict__ g1, const float* __restrict__ be1,
    const float* __restrict__ W2, const float* __restrict__ b2,
    const float* __restrict__ gf, const float* __restrict__ bf,
    float* __restrict__ outf)
{
    __shared__ float sb1[HF], sg1[HF], sbe1[HF];
    __shared__ float sb2[CF], sgf[CF], sbf[CF];
    __shared__ float sfi[CF], sh[HF];
    __shared__ float sred[8];

    const int tid = threadIdx.x;
    if (tid < HF) { sb1[tid] = b1[tid]; sg1[tid] = g1[tid]; sbe1[tid] = be1[tid]; }
    if (tid < CF) { sb2[tid] = b2[tid]; sgf[tid] = gf[tid]; sbf[tid] = bf[tid]; }
    __syncthreads();

    const int w = tid >> 5, l = tid & 31;

    for (int row = blockIdx.x; row < M_Q; row += gridDim.x) {
        if (tid < CF) sfi[tid] = g_fi[(size_t)row * CF + tid];
        __syncthreads();

        float acc = 0.f;
#pragma unroll 16
        for (int c = 0; c < CF; c++)
            acc = __fmaf_rn(sfi[c], __ldg(&W1[c * HF + tid]), acc);
        const float x = fmaxf(__fadd_rn(acc, sb1[tid]), 0.f);

        float s = x, ssq = x * x;
        for (int o = 16; o; o >>= 1) {
            s   += __shfl_down_sync(0xffffffffu, s, o);
            ssq += __shfl_down_sync(0xffffffffu, ssq, o);
        }
        if (l == 0) { sred[w] = s; sred[4 + w] = ssq; }
        __syncthreads();
        {
            const float S  = sred[0] + sred[1] + sred[2] + sred[3];
            const float SS = sred[4] + sred[5] + sred[6] + sred[7];
            const float mu  = S * (1.0f / HF);
            const float var = SS * (1.0f / HF) - mu * mu;
            const float rstd = 1.0f / sqrtf(var + 1e-5f);
            sh[tid] = (x - mu) * rstd * sg1[tid] + sbe1[tid];
        }
        __syncthreads();

        float fo = 0.f;
        if (tid < CF) {
            float a2 = 0.f;
#pragma unroll 16
            for (int h = 0; h < HF; h++)
                a2 = __fmaf_rn(sh[h], __ldg(&W2[h * CF + tid]), a2);
            fo = __fadd_rn(__fadd_rn(a2, sb2[tid]), sfi[tid]);
        }

        float s2 = (tid < CF) ? fo : 0.f;
        float ss2 = s2 * s2;
        for (int o = 16; o; o >>= 1) {
            s2  += __shfl_down_sync(0xffffffffu, s2, o);
            ss2 += __shfl_down_sync(0xffffffffu, ss2, o);
        }
        if (l == 0) { sred[w] = s2; sred[4 + w] = ss2; }
        __syncthreads();
        {
            const float S  = sred[0] + sred[1] + sred[2] + sred[3];
            const float SS = sred[4] + sred[5] + sred[6] + sred[7];
            const float mu  = S * (1.0f / CF);
            const float var = SS * (1.0f / CF) - mu * mu;
            const float rstd = 1.0f / sqrtf(var + 1e-5f);
            if (tid < CF) {
                const float z = (fo - mu) * rstd * sgf[tid] + sbf[tid];
                outf[(size_t)row * CF + tid] = tanhf(z) * 6.0f;
            }
        }
        __syncthreads();
    }
}

// ---------------------------------------------------------------------------
// Kernel 4: pass-through copy of gt_coords into the output head.
// ---------------------------------------------------------------------------
__global__ void copy_kernel(const float* __restrict__ src, float* __restrict__ dst, int n)
{
    int i = blockIdx.x * blockDim.x + threadIdx.x;
    if (i < n) dst[i] = src[i];
}

extern "C" void kernel_launch(void* const* d_in, const int* in_sizes, int n_in,
                              void* d_out, int out_size)
{
    const float* coords = (const float*)d_in[0];
    const float* feats  = (const float*)d_in[1];
    const float* gt     = (const float*)d_in[2];
    const float* W1     = (const float*)d_in[3];
    const float* b1     = (const float*)d_in[4];
    const float* g1     = (const float*)d_in[5];
    const float* be1    = (const float*)d_in[6];
    const float* W2     = (const float*)d_in[7];
    const float* b2     = (const float*)d_in[8];
    const float* gf     = (const float*)d_in[9];
    const float* bf     = (const float*)d_in[10];

    float* out = (float*)d_out;
    float* out_feats = out;

    if (out_size >= M_Q * 3 + M_Q * CF) {
        copy_kernel<<<(M_Q * 3 + 255) / 256, 256>>>(gt, out, M_Q * 3);
        out_feats = out + M_Q * 3;
    }

    stats_rowred_kernel<<<3, 1024>>>(coords, gt);
    presrc_kernel<<<(N_SRC + 255) / 256, 256>>>(coords);

    dim3 kgrid((M_Q + 255) / 256, NSPLIT);
    knn_partial_kernel<<<kgrid, 256>>>(gt);
    knn_merge_kernel<<<(M_Q + 255) / 256, 256>>>(feats);

    mlp_kernel<<<2048, 128>>>(W1, b1, g1, be1, W2, b2, gf, bf, out_feats);
}

// round 16
// speedup vs baseline: 1.8958x; 1.2001x over previous
#include <cuda_runtime.h>
#include <math.h>

#define N_SRC 20000
#define M_Q   40000
#define N_ALL 60000
#define CF    64
#define HF    128
#define NSPLIT 5
#define SPLEN  4000          // N_SRC / NSPLIT
#define TS     2000          // tile: SPLEN = 2*TS exactly

typedef unsigned long long u64;

__device__ float g_stats[6];                 // mu[3], sd[3]
__device__ float g_fi[(size_t)M_Q * CF];     // interpolated features
__device__ float4 g_src[N_SRC];              // standardized sources + s2
__device__ float g_pd[(size_t)M_Q * NSPLIT * 3];  // partial top-3 dists
__device__ int   g_pi[(size_t)M_Q * NSPLIT * 3];  // partial top-3 indices

// ---------------------------------------------------------------------------
// Packed f32x2 helpers (per-lane IEEE RN — bit-identical to scalar ops).
// ---------------------------------------------------------------------------
__device__ __forceinline__ u64 pk2(float a, float b)
{ u64 r; asm("mov.b64 %0, {%1, %2};" : "=l"(r) : "f"(a), "f"(b)); return r; }
__device__ __forceinline__ void upk2(u64 v, float& a, float& b)
{ asm("mov.b64 {%0, %1}, %2;" : "=f"(a), "=f"(b) : "l"(v)); }
__device__ __forceinline__ u64 mul2(u64 a, u64 b)
{ u64 r; asm("mul.rn.f32x2 %0, %1, %2;" : "=l"(r) : "l"(a), "l"(b)); return r; }
__device__ __forceinline__ u64 add2(u64 a, u64 b)
{ u64 r; asm("add.rn.f32x2 %0, %1, %2;" : "=l"(r) : "l"(a), "l"(b)); return r; }
__device__ __forceinline__ u64 sub2(u64 a, u64 b)
{ u64 r; asm("sub.rn.f32x2 %0, %1, %2;" : "=l"(r) : "l"(a), "l"(b)); return r; }
__device__ __forceinline__ u64 lo2(const float4& v)
{ u64 r; memcpy(&r, &v.x, 8); return r; }
__device__ __forceinline__ u64 hi2(const float4& v)
{ u64 r; memcpy(&r, &v.z, 8); return r; }

// ---------------------------------------------------------------------------
// Kernel 1: stats — F2 bit-family (row-reduce 1024 thr, vec=2). LOCKED.
// ---------------------------------------------------------------------------
__device__ __forceinline__ float load_col(const float* __restrict__ coords,
                                          const float* __restrict__ gt,
                                          int r, int c)
{
    return (r < M_Q) ? gt[r * 3 + c] : coords[(r - M_Q) * 3 + c];
}

__global__ void __launch_bounds__(1024) stats_rowred_kernel(
    const float* __restrict__ coords, const float* __restrict__ gt)
{
    const int c    = blockIdx.x;
    const int t    = threadIdx.x;
    const int lane = t & 31;
    const int w    = t >> 5;
    __shared__ float part[32];
    __shared__ float smu;

    float a0 = 0.f, a1 = 0.f;
    for (int i = 0; i < 30; i++) {
        const int e0 = 2 * t + 2048 * i;
        const int e1 = e0 + 1;
        if (e0 < N_ALL) a0 = __fadd_rn(a0, load_col(coords, gt, e0, c));
        if (e1 < N_ALL) a1 = __fadd_rn(a1, load_col(coords, gt, e1, c));
    }
    float p = __fadd_rn(a0, a1);
#pragma unroll
    for (int off = 16; off; off >>= 1)
        p = __fadd_rn(p, __shfl_down_sync(0xffffffffu, p, off));
    if (lane == 0) part[w] = p;
    __syncthreads();
    if (w == 0) {
        float v = part[lane];
#pragma unroll
        for (int off = 16; off; off >>= 1)
            v = __fadd_rn(v, __shfl_down_sync(0xffffffffu, v, off));
        if (lane == 0) { smu = __fdiv_rn(v, 60000.0f); g_stats[c] = smu; }
    }
    __syncthreads();
    const float mu = smu;

    a0 = 0.f; a1 = 0.f;
    for (int i = 0; i < 30; i++) {
        const int e0 = 2 * t + 2048 * i;
        const int e1 = e0 + 1;
        if (e0 < N_ALL) {
            const float d = __fsub_rn(load_col(coords, gt, e0, c), mu);
            a0 = __fadd_rn(a0, __fmul_rn(d, d));
        }
        if (e1 < N_ALL) {
            const float d = __fsub_rn(load_col(coords, gt, e1, c), mu);
            a1 = __fadd_rn(a1, __fmul_rn(d, d));
        }
    }
    p = __fadd_rn(a0, a1);
#pragma unroll
    for (int off = 16; off; off >>= 1)
        p = __fadd_rn(p, __shfl_down_sync(0xffffffffu, p, off));
    if (lane == 0) part[w] = p;
    __syncthreads();
    if (w == 0) {
        float v = part[lane];
#pragma unroll
        for (int off = 16; off; off >>= 1)
            v = __fadd_rn(v, __shfl_down_sync(0xffffffffu, v, off));
        if (lane == 0) {
            float sd = __fsqrt_rn(__fdiv_rn(v, 59999.0f));
            if (fabsf(sd) < 1e-8f) sd = 1.0f;
            g_stats[3 + c] = sd;
        }
    }
}

// ---------------------------------------------------------------------------
// Kernel 1b: pre-standardize sources once. LOCKED bits.
// ---------------------------------------------------------------------------
__global__ void presrc_kernel(const float* __restrict__ coords)
{
    const int i = blockIdx.x * blockDim.x + threadIdx.x;
    if (i >= N_SRC) return;
    const float x = __fdiv_rn(__fsub_rn(coords[i * 3 + 0], g_stats[0]), g_stats[3]);
    const float y = __fdiv_rn(__fsub_rn(coords[i * 3 + 1], g_stats[1]), g_stats[4]);
    const float z = __fdiv_rn(__fsub_rn(coords[i * 3 + 2], g_stats[2]), g_stats[5]);
    const float s2 = __fadd_rn(__fadd_rn(__fmul_rn(x, x), __fmul_rn(y, y)),
                               __fmul_rn(z, z));
    g_src[i] = make_float4(x, y, z, s2);
}

// ---------------------------------------------------------------------------
// Stable top-3 insertion (strict '<', ascending-index order). LOCKED.
// ---------------------------------------------------------------------------
__device__ __forceinline__ void ins3(float d, int sidx,
                                     float& t0, float& t1, float& t2,
                                     int& i0, int& i1, int& i2)
{
    if (d < t2) {
        if (d < t1) {
            t2 = t1; i2 = i1;
            if (d < t0) { t1 = t0; i1 = i0; t0 = d; i0 = sidx; }
            else        { t1 = d;  i1 = sidx; }
        } else { t2 = d; i2 = sidx; }
    }
}

// ---------------------------------------------------------------------------
// Kernel 2a: per-split stable top-3, PACKED f32x2 distance evaluation.
// Per packed lane:  dot = ((qx*sx + qy*sy) + qz*sz)  (mul2/add2, no fma),
// d2 = (q2+s2) - (t+t) (add2/sub2) — per-lane RN identical to the scalar
// locked chain, so every d2 is bit-identical to R15's.
// SoA tile; float4 loads give aligned register pairs for the packed ops.
// ---------------------------------------------------------------------------
__global__ void __launch_bounds__(256) knn_partial_kernel(
    const float* __restrict__ gt)
{
    __shared__ float sx[TS], sy[TS], sz[TS], ss[TS];

    const int split = blockIdx.y;
    const int q = blockIdx.x * blockDim.x + threadIdx.x;
    const bool valid = (q < M_Q);

    const float mux = g_stats[0], muy = g_stats[1], muz = g_stats[2];
    const float sdx = g_stats[3], sdy = g_stats[4], sdz = g_stats[5];

    float qx = 0.f, qy = 0.f, qz = 0.f, q2 = 0.f;
    if (valid) {
        qx = __fdiv_rn(__fsub_rn(gt[q * 3 + 0], mux), sdx);
        qy = __fdiv_rn(__fsub_rn(gt[q * 3 + 1], muy), sdy);
        qz = __fdiv_rn(__fsub_rn(gt[q * 3 + 2], muz), sdz);
        q2 = __fadd_rn(__fadd_rn(__fmul_rn(qx, qx), __fmul_rn(qy, qy)),
                       __fmul_rn(qz, qz));
    }
    const u64 qx2 = pk2(qx, qx);
    const u64 qy2 = pk2(qy, qy);
    const u64 qz2 = pk2(qz, qz);
    const u64 q22 = pk2(q2, q2);

    float t0 = 3.4e38f, t1 = 3.4e38f, t2 = 3.4e38f;
    int   i0 = 0, i1 = 0, i2 = 0;

    const int sbase = split * SPLEN;
#pragma unroll
    for (int ti = 0; ti < SPLEN / TS; ti++) {
        const int base = sbase + ti * TS;
        __syncthreads();
        for (int j = threadIdx.x; j < TS; j += blockDim.x) {
            const float4 v = g_src[base + j];
            sx[j] = v.x; sy[j] = v.y; sz[j] = v.z; ss[j] = v.w;
        }
        __syncthreads();

#pragma unroll 4
        for (int j = 0; j < TS; j += 4) {
            const float4 X = *(const float4*)&sx[j];
            const float4 Y = *(const float4*)&sy[j];
            const float4 Z = *(const float4*)&sz[j];
            const float4 S = *(const float4*)&ss[j];

            // low pair: sources j, j+1
            u64 tl = add2(add2(mul2(qx2, lo2(X)), mul2(qy2, lo2(Y))),
                          mul2(qz2, lo2(Z)));
            u64 dl = sub2(add2(q22, lo2(S)), add2(tl, tl));
            // high pair: sources j+2, j+3
            u64 th = add2(add2(mul2(qx2, hi2(X)), mul2(qy2, hi2(Y))),
                          mul2(qz2, hi2(Z)));
            u64 dh = sub2(add2(q22, hi2(S)), add2(th, th));

            float d0, d1, d2, d3;
            upk2(dl, d0, d1);
            upk2(dh, d2, d3);

            const float m = fminf(fminf(d0, d1), fminf(d2, d3));
            if (m < t2) {
                ins3(d0, base + j + 0, t0, t1, t2, i0, i1, i2);
                ins3(d1, base + j + 1, t0, t1, t2, i0, i1, i2);
                ins3(d2, base + j + 2, t0, t1, t2, i0, i1, i2);
                ins3(d3, base + j + 3, t0, t1, t2, i0, i1, i2);
            }
        }
    }

    if (!valid) return;
    const size_t o = ((size_t)q * NSPLIT + split) * 3;
    g_pd[o + 0] = t0; g_pd[o + 1] = t1; g_pd[o + 2] = t2;
    g_pi[o + 0] = i0; g_pi[o + 1] = i1; g_pi[o + 2] = i2;
}

// ---------------------------------------------------------------------------
// Kernel 2b: merge partial top-3s (split-ascending, stable) + softmax +
// feature gather. Epilogue numerics LOCKED.
// ---------------------------------------------------------------------------
__global__ void __launch_bounds__(256) knn_merge_kernel(
    const float* __restrict__ feats)
{
    const int q = blockIdx.x * blockDim.x + threadIdx.x;
    if (q >= M_Q) return;

    float t0 = 3.4e38f, t1 = 3.4e38f, t2 = 3.4e38f;
    int   i0 = 0, i1 = 0, i2 = 0;
    const size_t ob = (size_t)q * NSPLIT * 3;
#pragma unroll
    for (int s = 0; s < NSPLIT * 3; s++)
        ins3(g_pd[ob + s], g_pi[ob + s], t0, t1, t2, i0, i1, i2);

    const float b0 = __fsqrt_rn(fmaxf(t0, 0.f));
    const float b1 = __fsqrt_rn(fmaxf(t1, 0.f));
    const float b2 = __fsqrt_rn(fmaxf(t2, 0.f));
    const float mean3 = __fdiv_rn(__fadd_rn(__fadd_rn(b0, b1), b2), 3.0f);
    const float scale = fmaxf(mean3, 1e-8f);
    const float e1 = expf(-__fdiv_rn(__fsub_rn(b1, b0), scale));
    const float e2 = expf(-__fdiv_rn(__fsub_rn(b2, b0), scale));
    const float sum = __fadd_rn(__fadd_rn(1.0f, e1), e2);
    const float w0 = __fdiv_rn(1.0f, sum);
    const float w1 = __fdiv_rn(e1, sum);
    const float w2 = __fdiv_rn(e2, sum);

    const float4* f0 = (const float4*)(feats + (size_t)i0 * CF);
    const float4* f1 = (const float4*)(feats + (size_t)i1 * CF);
    const float4* f2 = (const float4*)(feats + (size_t)i2 * CF);
    float4* outp = (float4*)(g_fi + (size_t)q * CF);
#pragma unroll
    for (int k = 0; k < CF / 4; k++) {
        const float4 A = f0[k], B = f1[k], Cc = f2[k];
        float4 r;
        r.x = __fadd_rn(__fadd_rn(__fmul_rn(w0, A.x), __fmul_rn(w1, B.x)), __fmul_rn(w2, Cc.x));
        r.y = __fadd_rn(__fadd_rn(__fmul_rn(w0, A.y), __fmul_rn(w1, B.y)), __fmul_rn(w2, Cc.y));
        r.z = __fadd_rn(__fadd_rn(__fmul_rn(w0, A.z), __fmul_rn(w1, B.z)), __fmul_rn(w2, Cc.z));
        r.w = __fadd_rn(__fadd_rn(__fmul_rn(w0, A.w), __fmul_rn(w1, B.w)), __fmul_rn(w2, Cc.w));
        outp[k] = r;
    }
}

// ---------------------------------------------------------------------------
// Kernel 3: per-row MLP (unchanged from R15 — bits locked).
// ---------------------------------------------------------------------------
__global__ void __launch_bounds__(128) mlp_kernel(
    const float* __restrict__ W1, const float* __restrict__ b1,
    const float* __restrict__ g1, const float* __restrict__ be1,
    const float* __restrict__ W2, const float* __restrict__ b2,
    const float* __restrict__ gf, const float* __restrict__ bf,
    float* __restrict__ outf)
{
    __shared__ float sb1[HF], sg1[HF], sbe1[HF];
    __shared__ float sb2[CF], sgf[CF], sbf[CF];
    __shared__ float sfi[CF], sh[HF];
    __shared__ float sred[8];

    const int tid = threadIdx.x;
    if (tid < HF) { sb1[tid] = b1[tid]; sg1[tid] = g1[tid]; sbe1[tid] = be1[tid]; }
    if (tid < CF) { sb2[tid] = b2[tid]; sgf[tid] = gf[tid]; sbf[tid] = bf[tid]; }
    __syncthreads();

    const int w = tid >> 5, l = tid & 31;

    for (int row = blockIdx.x; row < M_Q; row += gridDim.x) {
        if (tid < CF) sfi[tid] = g_fi[(size_t)row * CF + tid];
        __syncthreads();

        float acc = 0.f;
#pragma unroll 16
        for (int c = 0; c < CF; c++)
            acc = __fmaf_rn(sfi[c], __ldg(&W1[c * HF + tid]), acc);
        const float x = fmaxf(__fadd_rn(acc, sb1[tid]), 0.f);

        float s = x, ssq = x * x;
        for (int o = 16; o; o >>= 1) {
            s   += __shfl_down_sync(0xffffffffu, s, o);
            ssq += __shfl_down_sync(0xffffffffu, ssq, o);
        }
        if (l == 0) { sred[w] = s; sred[4 + w] = ssq; }
        __syncthreads();
        {
            const float S  = sred[0] + sred[1] + sred[2] + sred[3];
            const float SS = sred[4] + sred[5] + sred[6] + sred[7];
            const float mu  = S * (1.0f / HF);
            const float var = SS * (1.0f / HF) - mu * mu;
            const float rstd = 1.0f / sqrtf(var + 1e-5f);
            sh[tid] = (x - mu) * rstd * sg1[tid] + sbe1[tid];
        }
        __syncthreads();

        float fo = 0.f;
        if (tid < CF) {
            float a2 = 0.f;
#pragma unroll 16
            for (int h = 0; h < HF; h++)
                a2 = __fmaf_rn(sh[h], __ldg(&W2[h * CF + tid]), a2);
            fo = __fadd_rn(__fadd_rn(a2, sb2[tid]), sfi[tid]);
        }

        float s2 = (tid < CF) ? fo : 0.f;
        float ss2 = s2 * s2;
        for (int o = 16; o; o >>= 1) {
            s2  += __shfl_down_sync(0xffffffffu, s2, o);
            ss2 += __shfl_down_sync(0xffffffffu, ss2, o);
        }
        if (l == 0) { sred[w] = s2; sred[4 + w] = ss2; }
        __syncthreads();
        {
            const float S  = sred[0] + sred[1] + sred[2] + sred[3];
            const float SS = sred[4] + sred[5] + sred[6] + sred[7];
            const float mu  = S * (1.0f / CF);
            const float var = SS * (1.0f / CF) - mu * mu;
            const float rstd = 1.0f / sqrtf(var + 1e-5f);
            if (tid < CF) {
                const float z = (fo - mu) * rstd * sgf[tid] + sbf[tid];
                outf[(size_t)row * CF + tid] = tanhf(z) * 6.0f;
            }
        }
        __syncthreads();
    }
}

// ---------------------------------------------------------------------------
// Kernel 4: pass-through copy of gt_coords into the output head.
// ---------------------------------------------------------------------------
__global__ void copy_kernel(const float* __restrict__ src, float* __restrict__ dst, int n)
{
    int i = blockIdx.x * blockDim.x + threadIdx.x;
    if (i < n) dst[i] = src[i];
}

extern "C" void kernel_launch(void* const* d_in, const int* in_sizes, int n_in,
                              void* d_out, int out_size)
{
    const float* coords = (const float*)d_in[0];
    const float* feats  = (const float*)d_in[1];
    const float* gt     = (const float*)d_in[2];
    const float* W1     = (const float*)d_in[3];
    const float* b1     = (const float*)d_in[4];
    const float* g1     = (const float*)d_in[5];
    const float* be1    = (const float*)d_in[6];
    const float* W2     = (const float*)d_in[7];
    const float* b2     = (const float*)d_in[8];
    const float* gf     = (const float*)d_in[9];
    const float* bf     = (const float*)d_in[10];

    float* out = (float*)d_out;
    float* out_feats = out;

    if (out_size >= M_Q * 3 + M_Q * CF) {
        copy_kernel<<<(M_Q * 3 + 255) / 256, 256>>>(gt, out, M_Q * 3);
        out_feats = out + M_Q * 3;
    }

    stats_rowred_kernel<<<3, 1024>>>(coords, gt);
    presrc_kernel<<<(N_SRC + 255) / 256, 256>>>(coords);

    dim3 kgrid((M_Q + 255) / 256, NSPLIT);
    knn_partial_kernel<<<kgrid, 256>>>(gt);
    knn_merge_kernel<<<(M_Q + 255) / 256, 256>>>(feats);

    mlp_kernel<<<2048, 128>>>(W1, b1, g1, be1, W2, b2, gf, bf, out_feats);
}

// round 17
// speedup vs baseline: 2.1683x; 1.1437x over previous
#include <cuda_runtime.h>
#include <math.h>

#define N_SRC 20000
#define M_Q   40000
#define N_ALL 60000
#define CF    64
#define HF    128
#define NSPLIT 10
#define SPLEN  2000          // N_SRC / NSPLIT
#define TS     2000          // single tile per split

typedef unsigned long long u64;

__device__ float g_stats[6];                 // mu[3], sd[3]
__device__ float g_fi[(size_t)M_Q * CF];     // interpolated features
__device__ float4 g_src[N_SRC];              // standardized sources + s2
__device__ float g_pd[(size_t)M_Q * NSPLIT * 3];  // partial top-3 dists
__device__ int   g_pi[(size_t)M_Q * NSPLIT * 3];  // partial top-3 indices

// ---------------------------------------------------------------------------
// Packed f32x2 helpers.
// ---------------------------------------------------------------------------
__device__ __forceinline__ u64 pk2(float a, float b)
{ u64 r; asm("mov.b64 %0, {%1, %2};" : "=l"(r) : "f"(a), "f"(b)); return r; }
__device__ __forceinline__ void upk2(u64 v, float& a, float& b)
{ asm("mov.b64 {%0, %1}, %2;" : "=f"(a), "=f"(b) : "l"(v)); }
__device__ __forceinline__ u64 mul2(u64 a, u64 b)
{ u64 r; asm("mul.rn.f32x2 %0, %1, %2;" : "=l"(r) : "l"(a), "l"(b)); return r; }
__device__ __forceinline__ u64 add2(u64 a, u64 b)
{ u64 r; asm("add.rn.f32x2 %0, %1, %2;" : "=l"(r) : "l"(a), "l"(b)); return r; }
__device__ __forceinline__ u64 sub2(u64 a, u64 b)
{ u64 r; asm("sub.rn.f32x2 %0, %1, %2;" : "=l"(r) : "l"(a), "l"(b)); return r; }
__device__ __forceinline__ u64 lo2(const float4& v)
{ u64 r; memcpy(&r, &v.x, 8); return r; }
__device__ __forceinline__ u64 hi2(const float4& v)
{ u64 r; memcpy(&r, &v.z, 8); return r; }

// ---------------------------------------------------------------------------
// Kernel 1: stats — F2 bit-family (row-reduce 1024 thr, vec=2). LOCKED.
// ---------------------------------------------------------------------------
__device__ __forceinline__ float load_col(const float* __restrict__ coords,
                                          const float* __restrict__ gt,
                                          int r, int c)
{
    return (r < M_Q) ? gt[r * 3 + c] : coords[(r - M_Q) * 3 + c];
}

__global__ void __launch_bounds__(1024) stats_rowred_kernel(
    const float* __restrict__ coords, const float* __restrict__ gt)
{
    const int c    = blockIdx.x;
    const int t    = threadIdx.x;
    const int lane = t & 31;
    const int w    = t >> 5;
    __shared__ float part[32];
    __shared__ float smu;

    float a0 = 0.f, a1 = 0.f;
    for (int i = 0; i < 30; i++) {
        const int e0 = 2 * t + 2048 * i;
        const int e1 = e0 + 1;
        if (e0 < N_ALL) a0 = __fadd_rn(a0, load_col(coords, gt, e0, c));
        if (e1 < N_ALL) a1 = __fadd_rn(a1, load_col(coords, gt, e1, c));
    }
    float p = __fadd_rn(a0, a1);
#pragma unroll
    for (int off = 16; off; off >>= 1)
        p = __fadd_rn(p, __shfl_down_sync(0xffffffffu, p, off));
    if (lane == 0) part[w] = p;
    __syncthreads();
    if (w == 0) {
        float v = part[lane];
#pragma unroll
        for (int off = 16; off; off >>= 1)
            v = __fadd_rn(v, __shfl_down_sync(0xffffffffu, v, off));
        if (lane == 0) { smu = __fdiv_rn(v, 60000.0f); g_stats[c] = smu; }
    }
    __syncthreads();
    const float mu = smu;

    a0 = 0.f; a1 = 0.f;
    for (int i = 0; i < 30; i++) {
        const int e0 = 2 * t + 2048 * i;
        const int e1 = e0 + 1;
        if (e0 < N_ALL) {
            const float d = __fsub_rn(load_col(coords, gt, e0, c), mu);
            a0 = __fadd_rn(a0, __fmul_rn(d, d));
        }
        if (e1 < N_ALL) {
            const float d = __fsub_rn(load_col(coords, gt, e1, c), mu);
            a1 = __fadd_rn(a1, __fmul_rn(d, d));
        }
    }
    p = __fadd_rn(a0, a1);
#pragma unroll
    for (int off = 16; off; off >>= 1)
        p = __fadd_rn(p, __shfl_down_sync(0xffffffffu, p, off));
    if (lane == 0) part[w] = p;
    __syncthreads();
    if (w == 0) {
        float v = part[lane];
#pragma unroll
        for (int off = 16; off; off >>= 1)
            v = __fadd_rn(v, __shfl_down_sync(0xffffffffu, v, off));
        if (lane == 0) {
            float sd = __fsqrt_rn(__fdiv_rn(v, 59999.0f));
            if (fabsf(sd) < 1e-8f) sd = 1.0f;
            g_stats[3 + c] = sd;
        }
    }
}

// ---------------------------------------------------------------------------
// Kernel 1b: pre-standardize sources once. LOCKED bits.
// ---------------------------------------------------------------------------
__global__ void presrc_kernel(const float* __restrict__ coords)
{
    const int i = blockIdx.x * blockDim.x + threadIdx.x;
    if (i >= N_SRC) return;
    const float x = __fdiv_rn(__fsub_rn(coords[i * 3 + 0], g_stats[0]), g_stats[3]);
    const float y = __fdiv_rn(__fsub_rn(coords[i * 3 + 1], g_stats[1]), g_stats[4]);
    const float z = __fdiv_rn(__fsub_rn(coords[i * 3 + 2], g_stats[2]), g_stats[5]);
    const float s2 = __fadd_rn(__fadd_rn(__fmul_rn(x, x), __fmul_rn(y, y)),
                               __fmul_rn(z, z));
    g_src[i] = make_float4(x, y, z, s2);
}

// ---------------------------------------------------------------------------
// Stable top-3 insertion (strict '<', ascending-index order). LOCKED.
// ---------------------------------------------------------------------------
__device__ __forceinline__ void ins3(float d, int sidx,
                                     float& t0, float& t1, float& t2,
                                     int& i0, int& i1, int& i2)
{
    if (d < t2) {
        if (d < t1) {
            t2 = t1; i2 = i1;
            if (d < t0) { t1 = t0; i1 = i0; t0 = d; i0 = sidx; }
            else        { t1 = d;  i1 = sidx; }
        } else { t2 = d; i2 = sidx; }
    }
}

// ---------------------------------------------------------------------------
// Kernel 2a: per-split stable top-3, packed f32x2 distances (same chain as
// R16 — unchanged bits). NSPLIT=10 for occupancy; single 2000-source tile.
// ---------------------------------------------------------------------------
__global__ void __launch_bounds__(256) knn_partial_kernel(
    const float* __restrict__ gt)
{
    __shared__ float sx[TS], sy[TS], sz[TS], ss[TS];

    const int split = blockIdx.y;
    const int q = blockIdx.x * blockDim.x + threadIdx.x;
    const bool valid = (q < M_Q);

    const float mux = g_stats[0], muy = g_stats[1], muz = g_stats[2];
    const float sdx = g_stats[3], sdy = g_stats[4], sdz = g_stats[5];

    float qx = 0.f, qy = 0.f, qz = 0.f, q2 = 0.f;
    if (valid) {
        qx = __fdiv_rn(__fsub_rn(gt[q * 3 + 0], mux), sdx);
        qy = __fdiv_rn(__fsub_rn(gt[q * 3 + 1], muy), sdy);
        qz = __fdiv_rn(__fsub_rn(gt[q * 3 + 2], muz), sdz);
        q2 = __fadd_rn(__fadd_rn(__fmul_rn(qx, qx), __fmul_rn(qy, qy)),
                       __fmul_rn(qz, qz));
    }
    const u64 qx2 = pk2(qx, qx);
    const u64 qy2 = pk2(qy, qy);
    const u64 qz2 = pk2(qz, qz);
    const u64 q22 = pk2(q2, q2);

    float t0 = 3.4e38f, t1 = 3.4e38f, t2 = 3.4e38f;
    int   i0 = 0, i1 = 0, i2 = 0;

    const int base = split * SPLEN;
    for (int j = threadIdx.x; j < TS; j += blockDim.x) {
        const float4 v = g_src[base + j];
        sx[j] = v.x; sy[j] = v.y; sz[j] = v.z; ss[j] = v.w;
    }
    __syncthreads();

#pragma unroll 8
    for (int j = 0; j < TS; j += 4) {
        const float4 X = *(const float4*)&sx[j];
        const float4 Y = *(const float4*)&sy[j];
        const float4 Z = *(const float4*)&sz[j];
        const float4 S = *(const float4*)&ss[j];

        u64 tl = add2(add2(mul2(qx2, lo2(X)), mul2(qy2, lo2(Y))),
                      mul2(qz2, lo2(Z)));
        u64 dl = sub2(add2(q22, lo2(S)), add2(tl, tl));
        u64 th = add2(add2(mul2(qx2, hi2(X)), mul2(qy2, hi2(Y))),
                      mul2(qz2, hi2(Z)));
        u64 dh = sub2(add2(q22, hi2(S)), add2(th, th));

        float d0, d1, d2, d3;
        upk2(dl, d0, d1);
        upk2(dh, d2, d3);

        const float m = fminf(fminf(d0, d1), fminf(d2, d3));
        if (m < t2) {
            ins3(d0, base + j + 0, t0, t1, t2, i0, i1, i2);
            ins3(d1, base + j + 1, t0, t1, t2, i0, i1, i2);
            ins3(d2, base + j + 2, t0, t1, t2, i0, i1, i2);
            ins3(d3, base + j + 3, t0, t1, t2, i0, i1, i2);
        }
    }

    if (!valid) return;
    const size_t o = ((size_t)q * NSPLIT + split) * 3;
    g_pd[o + 0] = t0; g_pd[o + 1] = t1; g_pd[o + 2] = t2;
    g_pi[o + 0] = i0; g_pi[o + 1] = i1; g_pi[o + 2] = i2;
}

// ---------------------------------------------------------------------------
// Kernel 2b: merge partial top-3s (split-ascending, stable) + softmax +
// feature gather. Epilogue numerics LOCKED.
// ---------------------------------------------------------------------------
__global__ void __launch_bounds__(256) knn_merge_kernel(
    const float* __restrict__ feats)
{
    const int q = blockIdx.x * blockDim.x + threadIdx.x;
    if (q >= M_Q) return;

    float t0 = 3.4e38f, t1 = 3.4e38f, t2 = 3.4e38f;
    int   i0 = 0, i1 = 0, i2 = 0;
    const size_t ob = (size_t)q * NSPLIT * 3;
#pragma unroll
    for (int s = 0; s < NSPLIT * 3; s++)
        ins3(g_pd[ob + s], g_pi[ob + s], t0, t1, t2, i0, i1, i2);

    const float b0 = __fsqrt_rn(fmaxf(t0, 0.f));
    const float b1 = __fsqrt_rn(fmaxf(t1, 0.f));
    const float b2 = __fsqrt_rn(fmaxf(t2, 0.f));
    const float mean3 = __fdiv_rn(__fadd_rn(__fadd_rn(b0, b1), b2), 3.0f);
    const float scale = fmaxf(mean3, 1e-8f);
    const float e1 = expf(-__fdiv_rn(__fsub_rn(b1, b0), scale));
    const float e2 = expf(-__fdiv_rn(__fsub_rn(b2, b0), scale));
    const float sum = __fadd_rn(__fadd_rn(1.0f, e1), e2);
    const float w0 = __fdiv_rn(1.0f, sum);
    const float w1 = __fdiv_rn(e1, sum);
    const float w2 = __fdiv_rn(e2, sum);

    const float4* f0 = (const float4*)(feats + (size_t)i0 * CF);
    const float4* f1 = (const float4*)(feats + (size_t)i1 * CF);
    const float4* f2 = (const float4*)(feats + (size_t)i2 * CF);
    float4* outp = (float4*)(g_fi + (size_t)q * CF);
#pragma unroll
    for (int k = 0; k < CF / 4; k++) {
        const float4 A = f0[k], B = f1[k], Cc = f2[k];
        float4 r;
        r.x = __fadd_rn(__fadd_rn(__fmul_rn(w0, A.x), __fmul_rn(w1, B.x)), __fmul_rn(w2, Cc.x));
        r.y = __fadd_rn(__fadd_rn(__fmul_rn(w0, A.y), __fmul_rn(w1, B.y)), __fmul_rn(w2, Cc.y));
        r.z = __fadd_rn(__fadd_rn(__fmul_rn(w0, A.z), __fmul_rn(w1, B.z)), __fmul_rn(w2, Cc.z));
        r.w = __fadd_rn(__fadd_rn(__fmul_rn(w0, A.w), __fmul_rn(w1, B.w)), __fmul_rn(w2, Cc.w));
        outp[k] = r;
    }
}

// ---------------------------------------------------------------------------
// Kernel 3: per-row MLP — ONE WARP PER ROW (4 rows/block), no block syncs.
// Per-output fma chains identical (k-ascending); LN reductions use warp
// butterflies (order change is smooth, no ranking impact).
// ---------------------------------------------------------------------------
__global__ void __launch_bounds__(128) mlp_kernel(
    const float* __restrict__ W1, const float* __restrict__ b1,
    const float* __restrict__ g1, const float* __restrict__ be1,
    const float* __restrict__ W2, const float* __restrict__ b2,
    const float* __restrict__ gf, const float* __restrict__ bf,
    float* __restrict__ outf)
{
    __shared__ float sfi[4][CF];
    __shared__ float sh[4][HF];

    const int tid  = threadIdx.x;
    const int w    = tid >> 5;
    const int lane = tid & 31;
    const int row  = blockIdx.x * 4 + w;
    if (row >= M_Q) return;

    // load fi (2 per lane)
    sfi[w][lane]      = g_fi[(size_t)row * CF + lane];
    sfi[w][lane + 32] = g_fi[(size_t)row * CF + lane + 32];
    __syncwarp();

    // GEMV1: 4 outputs per lane (o = lane + 32u), k-ascending
    float acc0 = 0.f, acc1 = 0.f, acc2 = 0.f, acc3 = 0.f;
#pragma unroll 8
    for (int c = 0; c < CF; c++) {
        const float fic = sfi[w][c];
        acc0 = __fmaf_rn(fic, __ldg(&W1[c * HF + lane     ]), acc0);
        acc1 = __fmaf_rn(fic, __ldg(&W1[c * HF + lane + 32]), acc1);
        acc2 = __fmaf_rn(fic, __ldg(&W1[c * HF + lane + 64]), acc2);
        acc3 = __fmaf_rn(fic, __ldg(&W1[c * HF + lane + 96]), acc3);
    }
    const float x0 = fmaxf(__fadd_rn(acc0, b1[lane     ]), 0.f);
    const float x1 = fmaxf(__fadd_rn(acc1, b1[lane + 32]), 0.f);
    const float x2 = fmaxf(__fadd_rn(acc2, b1[lane + 64]), 0.f);
    const float x3 = fmaxf(__fadd_rn(acc3, b1[lane + 96]), 0.f);

    // LayerNorm over 128 (warp butterfly)
    float s  = ((x0 + x1) + (x2 + x3));
    float sq = ((x0 * x0 + x1 * x1) + (x2 * x2 + x3 * x3));
#pragma unroll
    for (int off = 16; off; off >>= 1) {
        s  += __shfl_xor_sync(0xffffffffu, s,  off);
        sq += __shfl_xor_sync(0xffffffffu, sq, off);
    }
    {
        const float mu   = s * (1.0f / HF);
        const float var  = sq * (1.0f / HF) - mu * mu;
        const float rstd = 1.0f / sqrtf(var + 1e-5f);
        sh[w][lane     ] = (x0 - mu) * rstd * g1[lane     ] + be1[lane     ];
        sh[w][lane + 32] = (x1 - mu) * rstd * g1[lane + 32] + be1[lane + 32];
        sh[w][lane + 64] = (x2 - mu) * rstd * g1[lane + 64] + be1[lane + 64];
        sh[w][lane + 96] = (x3 - mu) * rstd * g1[lane + 96] + be1[lane + 96];
    }
    __syncwarp();

    // GEMV2: 2 outputs per lane (o = lane, lane+32), k-ascending, +bias+resid
    float a0 = 0.f, a1 = 0.f;
#pragma unroll 8
    for (int h = 0; h < HF; h++) {
        const float hv = sh[w][h];
        a0 = __fmaf_rn(hv, __ldg(&W2[h * CF + lane     ]), a0);
        a1 = __fmaf_rn(hv, __ldg(&W2[h * CF + lane + 32]), a1);
    }
    const float fo0 = __fadd_rn(__fadd_rn(a0, b2[lane     ]), sfi[w][lane     ]);
    const float fo1 = __fadd_rn(__fadd_rn(a1, b2[lane + 32]), sfi[w][lane + 32]);

    // LayerNorm over 64 (warp butterfly)
    float s2  = fo0 + fo1;
    float sq2 = fo0 * fo0 + fo1 * fo1;
#pragma unroll
    for (int off = 16; off; off >>= 1) {
        s2  += __shfl_xor_sync(0xffffffffu, s2,  off);
        sq2 += __shfl_xor_sync(0xffffffffu, sq2, off);
    }
    {
        const float mu   = s2 * (1.0f / CF);
        const float var  = sq2 * (1.0f / CF) - mu * mu;
        const float rstd = 1.0f / sqrtf(var + 1e-5f);
        const float z0 = (fo0 - mu) * rstd * gf[lane     ] + bf[lane     ];
        const float z1 = (fo1 - mu) * rstd * gf[lane + 32] + bf[lane + 32];
        outf[(size_t)row * CF + lane     ] = tanhf(z0) * 6.0f;
        outf[(size_t)row * CF + lane + 32] = tanhf(z1) * 6.0f;
    }
}

// ---------------------------------------------------------------------------
// Kernel 4: pass-through copy of gt_coords into the output head.
// ---------------------------------------------------------------------------
__global__ void copy_kernel(const float* __restrict__ src, float* __restrict__ dst, int n)
{
    int i = blockIdx.x * blockDim.x + threadIdx.x;
    if (i < n) dst[i] = src[i];
}

extern "C" void kernel_launch(void* const* d_in, const int* in_sizes, int n_in,
                              void* d_out, int out_size)
{
    const float* coords = (const float*)d_in[0];
    const float* feats  = (const float*)d_in[1];
    const float* gt     = (const float*)d_in[2];
    const float* W1     = (const float*)d_in[3];
    const float* b1     = (const float*)d_in[4];
    const float* g1     = (const float*)d_in[5];
    const float* be1    = (const float*)d_in[6];
    const float* W2     = (const float*)d_in[7];
    const float* b2     = (const float*)d_in[8];
    const float* gf     = (const float*)d_in[9];
    const float* bf     = (const float*)d_in[10];

    float* out = (float*)d_out;
    float* out_feats = out;

    if (out_size >= M_Q * 3 + M_Q * CF) {
        copy_kernel<<<(M_Q * 3 + 255) / 256, 256>>>(gt, out, M_Q * 3);
        out_feats = out + M_Q * 3;
    }

    stats_rowred_kernel<<<3, 1024>>>(coords, gt);
    presrc_kernel<<<(N_SRC + 255) / 256, 256>>>(coords);

    dim3 kgrid((M_Q + 255) / 256, NSPLIT);
    knn_partial_kernel<<<kgrid, 256>>>(gt);
    knn_merge_kernel<<<(M_Q + 255) / 256, 256>>>(feats);

    mlp_kernel<<<(M_Q + 3) / 4, 128>>>(W1, b1, g1, be1, W2, b2, gf, bf, out_feats);
}